// round 6
// baseline (speedup 1.0000x reference)
#include <cuda_runtime.h>
#include <cstdint>

#define BATCH 384
#define FEAT  256
#define GROUP 8
#define RPB   4                  // pred rows per block
#define NBLK  (BATCH / RPB)      // 96 blocks <= 148 SMs -> spin barrier safe
#define NT    768                // threads: 8 k-eighths x 96 col-groups

// Scratch in device globals (no allocations allowed).
__device__ float g_gnT[FEAT * BATCH];       // normalized gallery, transposed [k][j]
__device__ float g_partial[NBLK];
__device__ unsigned g_bar  = 0;
__device__ unsigned g_done = 0;

__device__ __forceinline__ uint64_t pack2(float lo, float hi) {
    uint64_t r; asm("mov.b64 %0, {%1, %2};" : "=l"(r) : "f"(lo), "f"(hi)); return r;
}
__device__ __forceinline__ void unpack2(uint64_t v, float& lo, float& hi) {
    asm("mov.b64 {%0, %1}, %2;" : "=f"(lo), "=f"(hi) : "l"(v));
}
__device__ __forceinline__ void fma2(uint64_t& acc, uint64_t a, uint64_t b) {
    asm("fma.rn.f32x2 %0, %1, %2, %0;" : "+l"(acc) : "l"(a), "l"(b));
}
__device__ __forceinline__ float sigm(float d) {   // 1/(1+exp(clip(d*100)))
    float e = fminf(fmaxf(d * 100.0f, -50.0f), 50.0f);
    return __fdividef(1.0f, 1.0f + __expf(e));
}

__global__ __launch_bounds__(NT, 1) void smoothap_kernel(
        const float* __restrict__ preds,
        const float* __restrict__ gallery,
        float* __restrict__ out) {
    __shared__ uint64_t spp[RPB][FEAT];      // packed {p_r[k], p_r[k]} (8 KB)
    __shared__ float part[4][RPB][BATCH];    // split-K partials / staging (24 KB)
    __shared__ float S[RPB][BATCH];          // sims (6 KB)
    __shared__ float inv8[8];
    __shared__ float wp[24][2][8];           // per-warp rank partials (1.5 KB)
    __shared__ float wfin[3];
    __shared__ unsigned islast;

    int tid  = threadIdx.x;
    int warp = tid >> 5, lane = tid & 31;
    int base = blockIdx.x * RPB;

    // ---------------- Phase 0: stage + normalize ----------------
    float* stage = &part[0][0][0];           // [0..1023] preds, [1024..2047] gallery
    for (int idx = tid; idx < 2 * RPB * FEAT; idx += NT)
        stage[idx] = (idx < RPB * FEAT) ? preds[base * FEAT + idx]
                                        : gallery[base * FEAT + idx - RPB * FEAT];
    __syncthreads();

    if (warp < 8) {                          // warps 0-3 pred rows, 4-7 gallery rows
        const float* row = stage + warp * FEAT;
        float ss = 0.f;
        #pragma unroll
        for (int i = 0; i < FEAT / 32; i++) { float v = row[lane + 32 * i]; ss += v * v; }
        #pragma unroll
        for (int off = 16; off > 0; off >>= 1)
            ss += __shfl_down_sync(0xffffffffu, ss, off);
        if (lane == 0) inv8[warp] = 1.0f / fmaxf(sqrtf(ss), 1e-12f);
    }
    __syncthreads();

    for (int idx = tid; idx < RPB * FEAT; idx += NT) {  // pack pred rows {p,p}
        int r = idx >> 8, k = idx & 255;
        float v = stage[idx] * inv8[r];
        spp[r][k] = pack2(v, v);
        g_gnT[k * BATCH + base + r] = stage[RPB * FEAT + idx] * inv8[4 + r];
    }
    __syncthreads();

    // ---------------- Grid barrier (all 96 blocks wave-1 resident) ----------
    if (tid == 0) {
        __threadfence();
        atomicAdd(&g_bar, 1u);
        volatile unsigned* vb = &g_bar;
        while (*vb < (unsigned)NBLK) __nanosleep(20);
    }
    __syncthreads();

    // ---- Phase A: split-K GEMV, col-pair f32x2, 4-deep prefetched float4 ----
    int c4 = (tid % 96) * 4;                 // this thread's 4 columns
    int q  = tid / 96;                       // k-eighth: k in [32q, 32q+32)
    uint64_t accA[RPB], accB[RPB];           // {c4,c4+1} / {c4+2,c4+3} per row
    #pragma unroll
    for (int r = 0; r < RPB; r++) { accA[r] = 0ull; accB[r] = 0ull; }

    const float4* gp = (const float4*)&g_gnT[(q * 32) * BATCH + c4];
    float4 b0 = __ldcg(gp + 0 * 96);
    float4 b1 = __ldcg(gp + 1 * 96);
    float4 b2 = __ldcg(gp + 2 * 96);
    float4 b3 = __ldcg(gp + 3 * 96);
    gp += 4 * 96;

    #pragma unroll
    for (int kk = 0; kk < 32; kk += 4) {
        float4 n0, n1, n2, n3;
        if (kk < 28) {                       // compile-time resolved (full unroll)
            n0 = __ldcg(gp + 0 * 96);
            n1 = __ldcg(gp + 1 * 96);
            n2 = __ldcg(gp + 2 * 96);
            n3 = __ldcg(gp + 3 * 96);
            gp += 4 * 96;
        }
        int k = q * 32 + kk;
        #pragma unroll
        for (int r = 0; r < RPB; r++) {
            uint64_t p = spp[r][k + 0];
            fma2(accA[r], p, pack2(b0.x, b0.y));
            fma2(accB[r], p, pack2(b0.z, b0.w));
        }
        #pragma unroll
        for (int r = 0; r < RPB; r++) {
            uint64_t p = spp[r][k + 1];
            fma2(accA[r], p, pack2(b1.x, b1.y));
            fma2(accB[r], p, pack2(b1.z, b1.w));
        }
        #pragma unroll
        for (int r = 0; r < RPB; r++) {
            uint64_t p = spp[r][k + 2];
            fma2(accA[r], p, pack2(b2.x, b2.y));
            fma2(accB[r], p, pack2(b2.z, b2.w));
        }
        #pragma unroll
        for (int r = 0; r < RPB; r++) {
            uint64_t p = spp[r][k + 3];
            fma2(accA[r], p, pack2(b3.x, b3.y));
            fma2(accB[r], p, pack2(b3.z, b3.w));
        }
        b0 = n0; b1 = n1; b2 = n2; b3 = n3;
    }

    float a[RPB][4];                         // [row][col]
    #pragma unroll
    for (int r = 0; r < RPB; r++) {
        unpack2(accA[r], a[r][0], a[r][1]);
        unpack2(accB[r], a[r][2], a[r][3]);
    }
    __syncthreads();

    // split-K reduction tree (deterministic fixed order): 8 -> 4 -> 2 -> 1
    if (q >= 4) {
        #pragma unroll
        for (int r = 0; r < RPB; r++)
            *(float4*)&part[q - 4][r][c4] = make_float4(a[r][0], a[r][1], a[r][2], a[r][3]);
    }
    __syncthreads();
    if (q < 4) {
        #pragma unroll
        for (int r = 0; r < RPB; r++) {
            float4 v = *(const float4*)&part[q][r][c4];
            a[r][0] += v.x; a[r][1] += v.y; a[r][2] += v.z; a[r][3] += v.w;
        }
    }
    __syncthreads();
    if (q >= 2 && q < 4) {
        #pragma unroll
        for (int r = 0; r < RPB; r++)
            *(float4*)&part[q - 2][r][c4] = make_float4(a[r][0], a[r][1], a[r][2], a[r][3]);
    }
    __syncthreads();
    if (q < 2) {
        #pragma unroll
        for (int r = 0; r < RPB; r++) {
            float4 v = *(const float4*)&part[q][r][c4];
            a[r][0] += v.x; a[r][1] += v.y; a[r][2] += v.z; a[r][3] += v.w;
        }
    }
    __syncthreads();
    if (q == 1) {
        #pragma unroll
        for (int r = 0; r < RPB; r++)
            *(float4*)&part[0][r][c4] = make_float4(a[r][0], a[r][1], a[r][2], a[r][3]);
    }
    __syncthreads();
    if (q == 0) {
        #pragma unroll
        for (int r = 0; r < RPB; r++) {
            float4 v = *(const float4*)&part[0][r][c4];
            *(float4*)&S[r][c4] = make_float4(a[r][0] + v.x, a[r][1] + v.y,
                                              a[r][2] + v.z, a[r][3] + v.w);
        }
    }
    __syncthreads();

    // ---------------- Phase B: rank sums (2 rows per thread) ----------------
    int col  = tid % BATCH;
    int half = tid / BATCH;                  // 0 -> rows {0,1}, 1 -> rows {2,3}
    int n8   = base & ~(GROUP - 1);          // diagonal-block start column

    #pragma unroll
    for (int rr = 0; rr < 2; rr++) {
        int r = half * 2 + rr;
        float sval = S[r][col];
        float sg[8];
        #pragma unroll
        for (int b = 0; b < 8; b++) sg[b] = sigm(S[r][n8 + b] - sval);
        #pragma unroll
        for (int b = 0; b < 8; b++) {
            #pragma unroll
            for (int off = 16; off > 0; off >>= 1)
                sg[b] += __shfl_down_sync(0xffffffffu, sg[b], off);
        }
        if (lane == 0) {
            #pragma unroll
            for (int b = 0; b < 8; b++) wp[warp][rr][b] = sg[b];
        }
    }
    __syncthreads();

    float btotal = 0.f;
    if (tid < 32) {                          // one thread per (row, b)
        int r = tid >> 3, b = tid & 7;
        int w0 = (r >> 1) * 12, rr = r & 1;  // rows 0,1 -> warps 0-11; 2,3 -> 12-23
        float allrk = 0.f;
        #pragma unroll
        for (int w = 0; w < 12; w++) allrk += wp[w0 + w][rr][b];
        float db = S[r][n8 + b];
        float posrk = 0.f;
        #pragma unroll
        for (int c = 0; c < 8; c++) posrk += sigm(db - S[r][n8 + c]);
        float ratio = __fdividef(posrk, allrk);
        #pragma unroll
        for (int off = 16; off > 0; off >>= 1)
            ratio += __shfl_down_sync(0xffffffffu, ratio, off);
        btotal = ratio;
    }
    if (tid == 0) {
        g_partial[blockIdx.x] = btotal;
        __threadfence();
        islast = (atomicAdd(&g_done, 1u) == (unsigned)(NBLK - 1)) ? 1u : 0u;
    }
    __syncthreads();

    // ---------------- Final reduction by the last-done block ----------------
    if (islast) {
        if (tid < 96) {
            float v = __ldcg(&g_partial[tid]);
            #pragma unroll
            for (int off = 16; off > 0; off >>= 1)
                v += __shfl_down_sync(0xffffffffu, v, off);
            if (lane == 0) wfin[warp] = v;
        }
        __syncthreads();
        if (tid == 0) {
            float tot = wfin[0] + wfin[1] + wfin[2];
            out[0] = 1.0f - tot / (float)(GROUP * BATCH);
            g_bar  = 0;                      // reset for next graph replay
            g_done = 0;
        }
    }
}

extern "C" void kernel_launch(void* const* d_in, const int* in_sizes, int n_in,
                              void* d_out, int out_size) {
    const float* preds   = (const float*)d_in[0];
    const float* gallery = (const float*)d_in[1];
    float* out = (float*)d_out;
    smoothap_kernel<<<NBLK, NT>>>(preds, gallery, out);
}

// round 7
// speedup vs baseline: 1.1015x; 1.1015x over previous
#include <cuda_runtime.h>
#include <cstdint>

#define BATCH 384
#define FEAT  256
#define GROUP 8
#define RPB   3                  // pred rows per block (identity split is OK)
#define NBLK  (BATCH / RPB)      // 128 blocks <= 148 SMs -> spin barrier safe
#define NT    768                // threads: 8 k-eighths x 96 col-groups

// Scratch in device globals (no allocations allowed).
__device__ float g_gnT[FEAT * BATCH];       // normalized gallery, transposed [k][j]
__device__ float g_partial[NBLK];
__device__ unsigned g_bar  = 0;
__device__ unsigned g_done = 0;

__device__ __forceinline__ uint64_t pack2(float lo, float hi) {
    uint64_t r; asm("mov.b64 %0, {%1, %2};" : "=l"(r) : "f"(lo), "f"(hi)); return r;
}
__device__ __forceinline__ void unpack2(uint64_t v, float& lo, float& hi) {
    asm("mov.b64 {%0, %1}, %2;" : "=f"(lo), "=f"(hi) : "l"(v));
}
__device__ __forceinline__ void fma2(uint64_t& acc, uint64_t a, uint64_t b) {
    asm("fma.rn.f32x2 %0, %1, %2, %0;" : "+l"(acc) : "l"(a), "l"(b));
}
__device__ __forceinline__ float sigm(float d) {   // 1/(1+exp(clip(d*100)))
    float e = fminf(fmaxf(d * 100.0f, -50.0f), 50.0f);
    return __fdividef(1.0f, 1.0f + __expf(e));
}

__global__ __launch_bounds__(NT, 1) void smoothap_kernel(
        const float* __restrict__ preds,
        const float* __restrict__ gallery,
        float* __restrict__ out) {
    __shared__ uint64_t spp[RPB][FEAT];      // packed {p_r[k], p_r[k]} (6 KB)
    __shared__ float part[4][RPB][BATCH];    // split-K partials / staging (18 KB)
    __shared__ float S[RPB][BATCH];          // sims (4.5 KB)
    __shared__ float inv6[6];                // 3 pred + 3 gallery inverse norms
    __shared__ float wp[24][2][8];           // per-warp rank partials (1.5 KB)
    __shared__ float wfin[4];
    __shared__ unsigned islast;

    int tid  = threadIdx.x;
    int warp = tid >> 5, lane = tid & 31;
    int base = blockIdx.x * RPB;

    // ---------------- Phase 0: stage + normalize ----------------
    float* stage = &part[0][0][0];           // [0..767] preds, [768..1535] gallery
    for (int idx = tid; idx < 2 * RPB * FEAT; idx += NT)
        stage[idx] = (idx < RPB * FEAT) ? preds[base * FEAT + idx]
                                        : gallery[base * FEAT + idx - RPB * FEAT];
    __syncthreads();

    if (warp < 6) {                          // warps 0-2 pred rows, 3-5 gallery rows
        const float* row = stage + warp * FEAT;
        float ss = 0.f;
        #pragma unroll
        for (int i = 0; i < FEAT / 32; i++) { float v = row[lane + 32 * i]; ss += v * v; }
        #pragma unroll
        for (int off = 16; off > 0; off >>= 1)
            ss += __shfl_down_sync(0xffffffffu, ss, off);
        if (lane == 0) inv6[warp] = 1.0f / fmaxf(sqrtf(ss), 1e-12f);
    }
    __syncthreads();

    for (int idx = tid; idx < RPB * FEAT; idx += NT) {  // pack {p,p}; publish gnT
        int r = idx / FEAT, k = idx % FEAT;
        float v = stage[idx] * inv6[r];
        spp[r][k] = pack2(v, v);
        g_gnT[k * BATCH + base + r] = stage[RPB * FEAT + idx] * inv6[3 + r];
    }
    __syncthreads();

    // ---------------- Grid barrier (all 128 blocks wave-1 resident) ---------
    if (tid == 0) {
        __threadfence();
        atomicAdd(&g_bar, 1u);
        volatile unsigned* vb = &g_bar;
        while (*vb < (unsigned)NBLK) __nanosleep(20);
    }
    __syncthreads();

    // ---- Phase A: split-K GEMV, column-pair f32x2 (g-pairs free from LDG.128)
    int c4 = (tid % 96) * 4;                 // this thread's 4 columns
    int q  = tid / 96;                       // k-eighth: k in [32q, 32q+32)
    uint64_t accA[RPB], accB[RPB];           // {c4,c4+1} / {c4+2,c4+3} per row
    #pragma unroll
    for (int r = 0; r < RPB; r++) { accA[r] = 0ull; accB[r] = 0ull; }

    const float4* gp = (const float4*)&g_gnT[(q * 32) * BATCH + c4];
    #pragma unroll 4
    for (int kk = 0; kk < 32; kk++) {
        int k = q * 32 + kk;
        float4 g = __ldcg(gp); gp += BATCH / 4;
        uint64_t gxy = pack2(g.x, g.y);
        uint64_t gzw = pack2(g.z, g.w);
        #pragma unroll
        for (int r = 0; r < RPB; r++) {
            uint64_t p = spp[r][k];
            fma2(accA[r], p, gxy);
            fma2(accB[r], p, gzw);
        }
    }

    float a[RPB][4];                         // [row][col]
    #pragma unroll
    for (int r = 0; r < RPB; r++) {
        unpack2(accA[r], a[r][0], a[r][1]);
        unpack2(accB[r], a[r][2], a[r][3]);
    }
    __syncthreads();                         // stage (aliases part) fully consumed

    // split-K reduction tree (deterministic fixed order): 8 -> 4 -> 2 -> 1
    if (q >= 4) {
        #pragma unroll
        for (int r = 0; r < RPB; r++)
            *(float4*)&part[q - 4][r][c4] = make_float4(a[r][0], a[r][1], a[r][2], a[r][3]);
    }
    __syncthreads();
    if (q < 4) {
        #pragma unroll
        for (int r = 0; r < RPB; r++) {
            float4 v = *(const float4*)&part[q][r][c4];
            a[r][0] += v.x; a[r][1] += v.y; a[r][2] += v.z; a[r][3] += v.w;
        }
    }
    __syncthreads();
    if (q >= 2 && q < 4) {
        #pragma unroll
        for (int r = 0; r < RPB; r++)
            *(float4*)&part[q - 2][r][c4] = make_float4(a[r][0], a[r][1], a[r][2], a[r][3]);
    }
    __syncthreads();
    if (q < 2) {
        #pragma unroll
        for (int r = 0; r < RPB; r++) {
            float4 v = *(const float4*)&part[q][r][c4];
            a[r][0] += v.x; a[r][1] += v.y; a[r][2] += v.z; a[r][3] += v.w;
        }
    }
    __syncthreads();
    if (q == 1) {
        #pragma unroll
        for (int r = 0; r < RPB; r++)
            *(float4*)&part[0][r][c4] = make_float4(a[r][0], a[r][1], a[r][2], a[r][3]);
    }
    __syncthreads();
    if (q == 0) {
        #pragma unroll
        for (int r = 0; r < RPB; r++) {
            float4 v = *(const float4*)&part[0][r][c4];
            *(float4*)&S[r][c4] = make_float4(a[r][0] + v.x, a[r][1] + v.y,
                                              a[r][2] + v.z, a[r][3] + v.w);
        }
    }
    __syncthreads();

    // ---------------- Phase B: rank sums, 3 rows ----------------
    int col  = tid % BATCH;
    int half = tid / BATCH;                  // pass 1: row = half; pass 2: row 2

    {   // pass 1: rows 0 (warps 0-11) and 1 (warps 12-23)
        int r  = half;
        int n8 = (base + r) & ~(GROUP - 1);
        float sval = S[r][col];
        float sg[8];
        #pragma unroll
        for (int b = 0; b < 8; b++) sg[b] = sigm(S[r][n8 + b] - sval);
        #pragma unroll
        for (int b = 0; b < 8; b++) {
            #pragma unroll
            for (int off = 16; off > 0; off >>= 1)
                sg[b] += __shfl_down_sync(0xffffffffu, sg[b], off);
        }
        if (lane == 0) {
            #pragma unroll
            for (int b = 0; b < 8; b++) wp[warp][0][b] = sg[b];
        }
    }
    if (half == 0) {                         // pass 2: row 2 (warps 0-11)
        int n8 = (base + 2) & ~(GROUP - 1);
        float sval = S[2][col];
        float sg[8];
        #pragma unroll
        for (int b = 0; b < 8; b++) sg[b] = sigm(S[2][n8 + b] - sval);
        #pragma unroll
        for (int b = 0; b < 8; b++) {
            #pragma unroll
            for (int off = 16; off > 0; off >>= 1)
                sg[b] += __shfl_down_sync(0xffffffffu, sg[b], off);
        }
        if (lane == 0) {
            #pragma unroll
            for (int b = 0; b < 8; b++) wp[warp][1][b] = sg[b];
        }
    }
    __syncthreads();

    float btotal = 0.f;
    if (tid < 32) {                          // threads 0-23: one per (row, b)
        float ratio = 0.f;
        if (tid < 24) {
            int r = tid >> 3, b = tid & 7;
            // row0 -> wp[0..11][0]; row1 -> wp[12..23][0]; row2 -> wp[0..11][1]
            int w0 = (r == 1) ? 12 : 0;
            int s  = (r == 2) ? 1 : 0;
            float allrk = 0.f;
            #pragma unroll
            for (int w = 0; w < 12; w++) allrk += wp[w0 + w][s][b];
            int n8 = (base + r) & ~(GROUP - 1);
            float db = S[r][n8 + b];
            float posrk = 0.f;
            #pragma unroll
            for (int c = 0; c < 8; c++) posrk += sigm(db - S[r][n8 + c]);
            ratio = __fdividef(posrk, allrk);
        }
        #pragma unroll
        for (int off = 16; off > 0; off >>= 1)
            ratio += __shfl_down_sync(0xffffffffu, ratio, off);
        btotal = ratio;
    }
    if (tid == 0) {
        g_partial[blockIdx.x] = btotal;
        __threadfence();
        islast = (atomicAdd(&g_done, 1u) == (unsigned)(NBLK - 1)) ? 1u : 0u;
    }
    __syncthreads();

    // ---------------- Final reduction by the last-done block ----------------
    if (islast) {
        if (tid < NBLK) {
            float v = __ldcg(&g_partial[tid]);
            #pragma unroll
            for (int off = 16; off > 0; off >>= 1)
                v += __shfl_down_sync(0xffffffffu, v, off);
            if (lane == 0) wfin[warp] = v;
        }
        __syncthreads();
        if (tid == 0) {
            float tot = wfin[0] + wfin[1] + wfin[2] + wfin[3];
            out[0] = 1.0f - tot / (float)(GROUP * BATCH);
            g_bar  = 0;                      // reset for next graph replay
            g_done = 0;
        }
    }
}

extern "C" void kernel_launch(void* const* d_in, const int* in_sizes, int n_in,
                              void* d_out, int out_size) {
    const float* preds   = (const float*)d_in[0];
    const float* gallery = (const float*)d_in[1];
    float* out = (float*)d_out;
    smoothap_kernel<<<NBLK, NT>>>(preds, gallery, out);
}